// round 5
// baseline (speedup 1.0000x reference)
#include <cuda_runtime.h>
#include <math.h>
#include <stdint.h>

#define Bb 8
#define Ss 512
#define Hh 768
#define Ll 12
#define NHh 12
#define HDd 64
#define FFf 3072
#define NCc 6
#define MM (Bb*Ss)          // 4096 rows
#define BHn (Bb*NHh)        // 96

// ---------------- scratch (device globals; no allocs allowed) ----------------
__device__ float g_x[MM*Hh];
__device__ float g_q[MM*Hh];
__device__ float g_k[MM*Hh];
__device__ float g_v[MM*Hh];
__device__ float g_ctx[MM*Hh];
__device__ float g_t[MM*Hh];
__device__ float g_ff[MM*FFf];
__device__ float g_tab[129*HDd];
__device__ float g_avg[Bb*Hh];
__device__ float g_pool[Bb*Hh];
__device__ float g_S[(size_t)BHn*Ss*Ss];       // 100.7 MB attention scores/probs
__device__ float g_wbin[(size_t)BHn*Ss*132];   // 26 MB

// ---------------- relative-position sinusoid table [129,64] ----------------
__global__ void tab_init_kernel(float* tab) {
    for (int idx = threadIdx.x; idx < 129*HDd; idx += blockDim.x) {
        int pos = idx / HDd;
        int i   = idx % HDd;
        double expo = (double)(2*(i/2)) / 64.0;
        double ang  = (double)pos * pow(10000.0, -expo);
        tab[idx] = (i % 2 == 0) ? (float)sin(ang) : (float)cos(ang);
    }
}

// ---------------- embedding + LayerNorm ----------------
__global__ __launch_bounds__(256) void embed_ln_kernel(
    const int* __restrict__ ids, const float* __restrict__ we,
    const float* __restrict__ pe, const float* __restrict__ te,
    const float* __restrict__ g, const float* __restrict__ bt,
    float* __restrict__ out)
{
    int r = blockIdx.x;
    int s = r % Ss;
    int id = ids[r];
    int tid = threadIdx.x;
    __shared__ float red[8];
    float v[3];
    #pragma unroll
    for (int j = 0; j < 3; j++) {
        int c = tid + j*256;
        v[j] = we[(size_t)id*Hh + c] + pe[(size_t)s*Hh + c] + te[c];
    }
    float sm = v[0] + v[1] + v[2];
    for (int o = 16; o > 0; o >>= 1) sm += __shfl_xor_sync(0xffffffff, sm, o);
    if ((tid & 31) == 0) red[tid >> 5] = sm;
    __syncthreads();
    if (tid < 8) {
        float t = red[tid];
        for (int o = 4; o > 0; o >>= 1) t += __shfl_xor_sync(0xff, t, o);
        if (tid == 0) red[0] = t;
    }
    __syncthreads();
    float mu = red[0] * (1.0f/768.0f);
    __syncthreads();
    float d0 = v[0]-mu, d1 = v[1]-mu, d2 = v[2]-mu;
    float s2 = d0*d0 + d1*d1 + d2*d2;
    for (int o = 16; o > 0; o >>= 1) s2 += __shfl_xor_sync(0xffffffff, s2, o);
    if ((tid & 31) == 0) red[tid >> 5] = s2;
    __syncthreads();
    if (tid < 8) {
        float t = red[tid];
        for (int o = 4; o > 0; o >>= 1) t += __shfl_xor_sync(0xff, t, o);
        if (tid == 0) red[0] = t;
    }
    __syncthreads();
    float inv = rsqrtf(red[0] * (1.0f/768.0f) + 1e-12f);
    #pragma unroll
    for (int j = 0; j < 3; j++) {
        int c = tid + j*256;
        out[(size_t)r*Hh + c] = (v[j]-mu) * inv * g[c] + bt[c];
    }
}

// ---------------- add-residual + LayerNorm ----------------
__global__ __launch_bounds__(256) void add_ln_kernel(
    const float* __restrict__ x, const float* __restrict__ y,
    const float* __restrict__ g, const float* __restrict__ bt,
    float* __restrict__ out)
{
    int r = blockIdx.x;
    int tid = threadIdx.x;
    __shared__ float red[8];
    float v[3];
    #pragma unroll
    for (int j = 0; j < 3; j++) {
        int c = tid + j*256;
        v[j] = x[(size_t)r*Hh + c] + y[(size_t)r*Hh + c];
    }
    float sm = v[0] + v[1] + v[2];
    for (int o = 16; o > 0; o >>= 1) sm += __shfl_xor_sync(0xffffffff, sm, o);
    if ((tid & 31) == 0) red[tid >> 5] = sm;
    __syncthreads();
    if (tid < 8) {
        float t = red[tid];
        for (int o = 4; o > 0; o >>= 1) t += __shfl_xor_sync(0xff, t, o);
        if (tid == 0) red[0] = t;
    }
    __syncthreads();
    float mu = red[0] * (1.0f/768.0f);
    __syncthreads();
    float d0 = v[0]-mu, d1 = v[1]-mu, d2 = v[2]-mu;
    float s2 = d0*d0 + d1*d1 + d2*d2;
    for (int o = 16; o > 0; o >>= 1) s2 += __shfl_xor_sync(0xffffffff, s2, o);
    if ((tid & 31) == 0) red[tid >> 5] = s2;
    __syncthreads();
    if (tid < 8) {
        float t = red[tid];
        for (int o = 4; o > 0; o >>= 1) t += __shfl_xor_sync(0xff, t, o);
        if (tid == 0) red[0] = t;
    }
    __syncthreads();
    float inv = rsqrtf(red[0] * (1.0f/768.0f) + 1e-12f);
    #pragma unroll
    for (int j = 0; j < 3; j++) {
        int c = tid + j*256;
        out[(size_t)r*Hh + c] = (v[j]-mu) * inv * g[c] + bt[c];
    }
}

// ================= TF32 helpers =================
__device__ __forceinline__ uint32_t cvt_tf32(float x) {
    uint32_t u;
    asm("cvt.rna.tf32.f32 %0, %1;" : "=r"(u) : "f"(x));
    return u;
}
__device__ __forceinline__ void split_tf32(float x, uint32_t& hi, uint32_t& lo) {
    hi = cvt_tf32(x);
    lo = cvt_tf32(x - __uint_as_float(hi));
}
__device__ __forceinline__ void mma_tf32(float* c, const uint32_t* a, uint32_t b0, uint32_t b1) {
    asm volatile(
        "mma.sync.aligned.m16n8k8.row.col.f32.tf32.tf32.f32 "
        "{%0,%1,%2,%3}, {%4,%5,%6,%7}, {%8,%9}, {%0,%1,%2,%3};"
        : "+f"(c[0]), "+f"(c[1]), "+f"(c[2]), "+f"(c[3])
        : "r"(a[0]), "r"(a[1]), "r"(a[2]), "r"(a[3]), "r"(b0), "r"(b1));
}

// ================= TF32 GEMM: 128x128x16 tiles =================
#define AS_STRIDE 20
#define BS_STRIDE 136
#define AS_BUF 2560
#define BS_BUF 2176

__device__ __forceinline__ void tgemm_body(
    const float* __restrict__ A, const float* __restrict__ W,
    const float* __restrict__ bias, float* __restrict__ C,
    int N, int K, int act, int m0, int n0, uint32_t* sm)
{
    uint32_t* As = sm;
    uint32_t* Bs = sm + 2*AS_BUF;

    int tid = threadIdx.x;
    int lane = tid & 31, wid = tid >> 5;
    int wr = wid >> 2, wc = wid & 3;
    int g = lane >> 2, tg = lane & 3;

    float acc[4][4][4];
    #pragma unroll
    for (int mf = 0; mf < 4; mf++)
        #pragma unroll
        for (int nf = 0; nf < 4; nf++)
            #pragma unroll
            for (int i = 0; i < 4; i++) acc[mf][nf][i] = 0.0f;

    float4 pa[2], pb[2];
    #pragma unroll
    for (int j = 0; j < 2; j++) {
        int idx = tid + j*256;
        pa[j] = *(const float4*)&A[(size_t)(m0 + (idx>>2))*K + ((idx&3)<<2)];
        pb[j] = *(const float4*)&W[(size_t)(idx>>5)*N + n0 + ((idx&31)<<2)];
    }
    int buf = 0;
    #pragma unroll
    for (int j = 0; j < 2; j++) {
        int idx = tid + j*256;
        uint32_t* da = As + buf*AS_BUF + (idx>>2)*AS_STRIDE + ((idx&3)<<2);
        da[0]=cvt_tf32(pa[j].x); da[1]=cvt_tf32(pa[j].y); da[2]=cvt_tf32(pa[j].z); da[3]=cvt_tf32(pa[j].w);
        uint32_t* db = Bs + buf*BS_BUF + (idx>>5)*BS_STRIDE + ((idx&31)<<2);
        db[0]=cvt_tf32(pb[j].x); db[1]=cvt_tf32(pb[j].y); db[2]=cvt_tf32(pb[j].z); db[3]=cvt_tf32(pb[j].w);
    }
    __syncthreads();

    int nt = K >> 4;
    for (int t = 0; t < nt; t++) {
        if (t + 1 < nt) {
            int k0 = (t+1) << 4;
            #pragma unroll
            for (int j = 0; j < 2; j++) {
                int idx = tid + j*256;
                pa[j] = *(const float4*)&A[(size_t)(m0 + (idx>>2))*K + k0 + ((idx&3)<<2)];
                pb[j] = *(const float4*)&W[(size_t)(k0 + (idx>>5))*N + n0 + ((idx&31)<<2)];
            }
        }
        const uint32_t* Ab = As + buf*AS_BUF;
        const uint32_t* Bbp = Bs + buf*BS_BUF;
        #pragma unroll
        for (int k8 = 0; k8 < 2; k8++) {
            int kb = k8 * 8;
            uint32_t af[4][4];
            #pragma unroll
            for (int mf = 0; mf < 4; mf++) {
                int r = wr*64 + mf*16;
                af[mf][0] = Ab[(r+g  )*AS_STRIDE + kb+tg  ];
                af[mf][1] = Ab[(r+g+8)*AS_STRIDE + kb+tg  ];
                af[mf][2] = Ab[(r+g  )*AS_STRIDE + kb+tg+4];
                af[mf][3] = Ab[(r+g+8)*AS_STRIDE + kb+tg+4];
            }
            #pragma unroll
            for (int nf = 0; nf < 4; nf++) {
                int cn = wc*32 + nf*8 + g;
                uint32_t b0 = Bbp[(kb+tg  )*BS_STRIDE + cn];
                uint32_t b1 = Bbp[(kb+tg+4)*BS_STRIDE + cn];
                #pragma unroll
                for (int mf = 0; mf < 4; mf++)
                    mma_tf32(acc[mf][nf], af[mf], b0, b1);
            }
        }
        if (t + 1 < nt) {
            buf ^= 1;
            #pragma unroll
            for (int j = 0; j < 2; j++) {
                int idx = tid + j*256;
                uint32_t* da = As + buf*AS_BUF + (idx>>2)*AS_STRIDE + ((idx&3)<<2);
                da[0]=cvt_tf32(pa[j].x); da[1]=cvt_tf32(pa[j].y); da[2]=cvt_tf32(pa[j].z); da[3]=cvt_tf32(pa[j].w);
                uint32_t* db = Bs + buf*BS_BUF + (idx>>5)*BS_STRIDE + ((idx&31)<<2);
                db[0]=cvt_tf32(pb[j].x); db[1]=cvt_tf32(pb[j].y); db[2]=cvt_tf32(pb[j].z); db[3]=cvt_tf32(pb[j].w);
            }
        }
        __syncthreads();
    }

    #pragma unroll
    for (int mf = 0; mf < 4; mf++) {
        int r0 = m0 + wr*64 + mf*16 + g;
        #pragma unroll
        for (int nf = 0; nf < 4; nf++) {
            int c0 = n0 + wc*32 + nf*8 + tg*2;
            float bb0 = bias[c0], bb1 = bias[c0+1];
            float v00 = acc[mf][nf][0] + bb0;
            float v01 = acc[mf][nf][1] + bb1;
            float v10 = acc[mf][nf][2] + bb0;
            float v11 = acc[mf][nf][3] + bb1;
            if (act) {
                v00 = v00 * normcdff(v00);
                v01 = v01 * normcdff(v01);
                v10 = v10 * normcdff(v10);
                v11 = v11 * normcdff(v11);
            }
            *(float2*)&C[(size_t)r0*N + c0]     = make_float2(v00, v01);
            *(float2*)&C[(size_t)(r0+8)*N + c0] = make_float2(v10, v11);
        }
    }
}

__global__ __launch_bounds__(256) void tgemm_kernel(
    const float* __restrict__ A, const float* __restrict__ W,
    const float* __restrict__ bias, float* __restrict__ C,
    int N, int K, int act)
{
    __shared__ uint32_t sm[2*AS_BUF + 2*BS_BUF];
    tgemm_body(A, W, bias, C, N, K, act, blockIdx.y*128, blockIdx.x*128, sm);
}

__global__ __launch_bounds__(256) void tgemm_qkv_kernel(
    const float* __restrict__ A,
    const float* __restrict__ Wq, const float* __restrict__ Wk, const float* __restrict__ Wv,
    const float* __restrict__ bq, const float* __restrict__ bk, const float* __restrict__ bv,
    float* __restrict__ q, float* __restrict__ k, float* __restrict__ v)
{
    __shared__ uint32_t sm[2*AS_BUF + 2*BS_BUF];
    int mat = blockIdx.x / 6;
    int bxx = blockIdx.x % 6;
    const float* W = (mat == 0) ? Wq : (mat == 1) ? Wk : Wv;
    const float* bi = (mat == 0) ? bq : (mat == 1) ? bk : bv;
    float* C = (mat == 0) ? q : (mat == 1) ? k : v;
    tgemm_body(A, W, bi, C, Hh, Hh, 0, blockIdx.y*128, bxx*128, sm);
}

// ================= fused attention front-end (tensor-core, split tf32) =================
// Computes S^T tiles via mma: A = K tile [j][d], B = Q^T [d][i].
// smem (uint32 words): Qthi 64*72 | Qtlo 64*72 | Khi 64*68 | Klo 64*68 | qw 64*132 (f32) | mb 512 (f32)
#define FS_QT   0
#define FS_QTLO 4608
#define FS_K    9216
#define FS_KLO  13568
#define FS_QW   17920
#define FS_MB   26368
#define FS_TOT  26880
#define FS_BYTES (FS_TOT*4)

__global__ __launch_bounds__(256) void attn_fused_kernel(
    const float* __restrict__ q, const float* __restrict__ k,
    const float* __restrict__ tab, const int* __restrict__ mask,
    float* S, float* __restrict__ wbin)
{
    extern __shared__ uint32_t us[];
    uint32_t* Qthi = us + FS_QT;
    uint32_t* Qtlo = us + FS_QTLO;
    uint32_t* Khi  = us + FS_K;
    uint32_t* Klo  = us + FS_KLO;
    float*    qw   = (float*)(us + FS_QW);
    float*    mb   = (float*)(us + FS_MB);

    const int b = blockIdx.z, h = blockIdx.y;
    const int i0 = blockIdx.x * 64;
    const int tid = threadIdx.x;
    const int lane = tid & 31, wid = tid >> 5;
    const int wr = wid >> 1, wc = wid & 1;
    const int g = lane >> 2, tg = lane & 3;
    const size_t base = ((size_t)b * Ss) * Hh + h * HDd;
    const size_t rbase = ((size_t)(b*NHh + h)) * Ss;

    for (int j = tid; j < Ss; j += 256)
        mb[j] = (1.0f - (float)mask[b*Ss + j]) * -10000.0f;

    // Q tile: load (i-major), transpose + split into Qt [d][i] stride 72
    for (int t = tid; t < 64*16; t += 256) {
        int i = t & 63, d0 = (t >> 6) << 2;
        float4 qv = *(const float4*)&q[base + (size_t)(i0 + i)*Hh + d0];
        #pragma unroll
        for (int w = 0; w < 4; w++) {
            uint32_t hi, lo;
            split_tf32((&qv.x)[w], hi, lo);
            Qthi[(d0 + w)*72 + i] = hi;
            Qtlo[(d0 + w)*72 + i] = lo;
        }
    }
    __syncthreads();

    // qrel: qw[i][c] = q_i . tab[c]  (scalar; q reconstructed from hi+lo)
    for (int e = tid; e < 64*129; e += 256) {
        int i = e & 63, c = e >> 6;
        const float* tb = tab + c*64;
        float s = 0.0f;
        #pragma unroll 8
        for (int d = 0; d < 64; d++) {
            float qv = __uint_as_float(Qthi[d*72 + i]) + __uint_as_float(Qtlo[d*72 + i]);
            s += qv * __ldg(&tb[d]);
        }
        qw[i*132 + c] = s;
    }

    // ---- score: 8 tiles of 64 keys; S^T = K @ Q^T via mma ----
    for (int jt = 0; jt < 8; jt++) {
        if (jt) __syncthreads();
        for (int t = tid; t < 64*16; t += 256) {
            int j = t >> 4, d0 = (t & 15) << 2;
            float4 kv = *(const float4*)&k[base + (size_t)(jt*64 + j)*Hh + d0];
            uint4 h4, l4;
            split_tf32(kv.x, h4.x, l4.x);
            split_tf32(kv.y, h4.y, l4.y);
            split_tf32(kv.z, h4.z, l4.z);
            split_tf32(kv.w, h4.w, l4.w);
            *(uint4*)&Khi[j*68 + d0] = h4;
            *(uint4*)&Klo[j*68 + d0] = l4;
        }
        __syncthreads();

        float acc[4][4];
        #pragma unroll
        for (int nf = 0; nf < 4; nf++)
            #pragma unroll
            for (int e = 0; e < 4; e++) acc[nf][e] = 0.0f;

        #pragma unroll
        for (int k8 = 0; k8 < 8; k8++) {
            int kb = k8*8;
            int r = wr*16;
            uint32_t ahi[4], alo[4];
            ahi[0] = Khi[(r+g  )*68 + kb+tg  ];
            ahi[1] = Khi[(r+g+8)*68 + kb+tg  ];
            ahi[2] = Khi[(r+g  )*68 + kb+tg+4];
            ahi[3] = Khi[(r+g+8)*68 + kb+tg+4];
            alo[0] = Klo[(r+g  )*68 + kb+tg  ];
            alo[1] = Klo[(r+g+8)*68 + kb+tg  ];
            alo[2] = Klo[(r+g  )*68 + kb+tg+4];
            alo[3] = Klo[(r+g+8)*68 + kb+tg+4];
            #pragma unroll
            for (int nf = 0; nf < 4; nf++) {
                int cn = wc*32 + nf*8 + g;
                uint32_t bh0 = Qthi[(kb+tg  )*72 + cn];
                uint32_t bh1 = Qthi[(kb+tg+4)*72 + cn];
                uint32_t bl0 = Qtlo[(kb+tg  )*72 + cn];
                uint32_t bl1 = Qtlo[(kb+tg+4)*72 + cn];
                mma_tf32(acc[nf], ahi, bh0, bh1);
                mma_tf32(acc[nf], ahi, bl0, bl1);
                mma_tf32(acc[nf], alo, bh0, bh1);
            }
        }

        // epilogue: element (key j, query i); add qrel + mask, write S[i][j]
        #pragma unroll
        for (int nf = 0; nf < 4; nf++) {
            int iloc0 = wc*32 + nf*8 + tg*2;
            #pragma unroll
            for (int e = 0; e < 4; e++) {
                int iloc = iloc0 + (e & 1);
                int jloc = wr*16 + g + ((e >> 1) << 3);
                int ig = i0 + iloc;
                int jg = jt*64 + jloc;
                int c = jg - ig; c = (c < -64) ? -64 : (c > 64 ? 64 : c); c += 64;
                S[(rbase + ig)*(size_t)Ss + jg] =
                    (acc[nf][e] + qw[iloc*132 + c]) * 0.125f + mb[jg];
            }
        }
    }
    __syncthreads();

    // ---- softmax + wbin gather (warp per row) ----
    {
        int wp = tid >> 5;
        for (int rr = wp; rr < 64; rr += 8) {
            int i = i0 + rr;
            float* srow = S + (rbase + i)*(size_t)Ss;
            float4* s4 = (float4*)srow;
            float4 x[4];
            #pragma unroll
            for (int qq = 0; qq < 4; qq++) x[qq] = s4[lane + 32*qq];

            float mx = -1e30f;
            #pragma unroll
            for (int qq = 0; qq < 4; qq++)
                mx = fmaxf(mx, fmaxf(fmaxf(x[qq].x, x[qq].y), fmaxf(x[qq].z, x[qq].w)));
            #pragma unroll
            for (int o = 16; o > 0; o >>= 1) mx = fmaxf(mx, __shfl_xor_sync(0xffffffff, mx, o));

            float sum = 0.0f;
            #pragma unroll
            for (int qq = 0; qq < 4; qq++) {
                x[qq].x = __expf(x[qq].x - mx); sum += x[qq].x;
                x[qq].y = __expf(x[qq].y - mx); sum += x[qq].y;
                x[qq].z = __expf(x[qq].z - mx); sum += x[qq].z;
                x[qq].w = __expf(x[qq].w - mx); sum += x[qq].w;
            }
            #pragma unroll
            for (int o = 16; o > 0; o >>= 1) sum += __shfl_xor_sync(0xffffffff, sum, o);
            float inv = 1.0f / sum;

            float* wrow = wbin + (rbase + i)*132;
            *(float4*)&wrow[lane*4] = make_float4(0.f,0.f,0.f,0.f);
            if (lane == 0) *(float4*)&wrow[128] = make_float4(0.f,0.f,0.f,0.f);
            __syncwarp();

            float lo = 0.0f, hi = 0.0f;
            #pragma unroll
            for (int qq = 0; qq < 4; qq++) {
                x[qq].x *= inv; x[qq].y *= inv; x[qq].z *= inv; x[qq].w *= inv;
                s4[lane + 32*qq] = x[qq];
                int jb = (lane + 32*qq) * 4;
                #pragma unroll
                for (int w = 0; w < 4; w++) {
                    int d = jb + w - i;
                    float pv = (&x[qq].x)[w];
                    if (d <= -64)      lo += pv;
                    else if (d >= 64)  hi += pv;
                    else               wrow[d + 64] = pv;
                }
            }
            #pragma unroll
            for (int o = 16; o > 0; o >>= 1) {
                lo += __shfl_xor_sync(0xffffffff, lo, o);
                hi += __shfl_xor_sync(0xffffffff, hi, o);
            }
            if (lane == 0) { wrow[0] = lo; wrow[128] = hi; }
        }
    }
}

// ================= attention ctx (tensor-core): ctx = P@V + wbin@tab =================
// 11 k-tiles: 8 of P@V (64 keys each) + 3 of wbin@tab (64 bins each, guarded)
#define CS_P   0
#define CS_PLO 4352
#define CS_V   8704
#define CS_VLO 13312
#define CS_TOT 17920
#define CS_BYTES (CS_TOT*4)

__global__ __launch_bounds__(256) void attn_ctx_kernel(
    const float* __restrict__ S, const float* __restrict__ v,
    const float* __restrict__ wbin, const float* __restrict__ tab,
    float* __restrict__ ctx)
{
    extern __shared__ uint32_t us[];
    uint32_t* Phi = us + CS_P;
    uint32_t* Plo = us + CS_PLO;
    uint32_t* Vhi = us + CS_V;
    uint32_t* Vlo = us + CS_VLO;

    const int b = blockIdx.z, h = blockIdx.y;
    const int i0 = blockIdx.x * 64;
    const int tid = threadIdx.x;
    const int lane = tid & 31, wid = tid >> 5;
    const int wr = wid >> 1, wc = wid & 1;
    const int g = lane >> 2, tg = lane & 3;
    const size_t base = ((size_t)b * Ss) * Hh + h * HDd;
    const size_t rbase = ((size_t)(b*NHh + h)) * Ss;

    float acc[4][4];
    #pragma unroll
    for (int nf = 0; nf < 4; nf++)
        #pragma unroll
        for (int e = 0; e < 4; e++) acc[nf][e] = 0.0f;

    for (int tile = 0; tile < 11; tile++) {
        if (tile) __syncthreads();
        if (tile < 8) {
            // A = P tile [i][j] stride 68
            for (int t = tid; t < 64*16; t += 256) {
                int i = t >> 4, j0 = (t & 15) << 2;
                float4 pv = *(const float4*)&S[(rbase + i0 + i)*(size_t)Ss + tile*64 + j0];
                uint4 h4, l4;
                split_tf32(pv.x, h4.x, l4.x);
                split_tf32(pv.y, h4.y, l4.y);
                split_tf32(pv.z, h4.z, l4.z);
                split_tf32(pv.w, h4.w, l4.w);
                *(uint4*)&Phi[i*68 + j0] = h4;
                *(uint4*)&Plo[i*68 + j0] = l4;
            }
            // B = V tile [j][d] stride 72
            for (int t = tid; t < 64*16; t += 256) {
                int j = t >> 4, d0 = (t & 15) << 2;
                float4 vv = *(const float4*)&v[base + (size_t)(tile*64 + j)*Hh + d0];
                uint4 h4, l4;
                split_tf32(vv.x, h4.x, l4.x);
                split_tf32(vv.y, h4.y, l4.y);
                split_tf32(vv.z, h4.z, l4.z);
                split_tf32(vv.w, h4.w, l4.w);
                *(uint4*)&Vhi[j*72 + d0] = h4;
                *(uint4*)&Vlo[j*72 + d0] = l4;
            }
        } else {
            int c0b = (tile - 8) * 64;
            // A = wbin tile [i][c] (guard c<129)
            for (int t = tid; t < 64*16; t += 256) {
                int i = t >> 4, c4 = (t & 15) << 2;
                uint4 h4, l4;
                #pragma unroll
                for (int w = 0; w < 4; w++) {
                    int c = c0b + c4 + w;
                    float val = (c < 129) ? wbin[(rbase + i0 + i)*132 + c] : 0.0f;
                    split_tf32(val, (&h4.x)[w], (&l4.x)[w]);
                }
                *(uint4*)&Phi[i*68 + c4] = h4;
                *(uint4*)&Plo[i*68 + c4] = l4;
            }
            // B = tab tile [c][d] (guard c<129)
            for (int t = tid; t < 64*16; t += 256) {
                int j = t >> 4, d0 = (t & 15) << 2;
                int c = c0b + j;
                float4 tv = (c < 129) ? *(const float4*)&tab[c*64 + d0]
                                      : make_float4(0.f,0.f,0.f,0.f);
                uint4 h4, l4;
                split_tf32(tv.x, h4.x, l4.x);
                split_tf32(tv.y, h4.y, l4.y);
                split_tf32(tv.z, h4.z, l4.z);
                split_tf32(tv.w, h4.w, l4.w);
                *(uint4*)&Vhi[j*72 + d0] = h4;
                *(uint4*)&Vlo[j*72 + d0] = l4;
            }
        }
        __syncthreads();

        #pragma unroll
        for (int k8 = 0; k8 < 8; k8++) {
            int kb = k8*8;
            int r = wr*16;
            uint32_t ahi[4], alo[4];
            ahi[0] = Phi[(r+g  )*68 + kb+tg  ];
            ahi[1] = Phi[(r+g+8)*68 + kb+tg  ];
            ahi[2] = Phi[(r+g  )*68 + kb+tg+4];
            ahi[3] = Phi[(r+g+8)*68 + kb+tg+4];
            alo[0] = Plo[(r+g  )*68 + kb+tg  ];
            alo[1] = Plo[(r+g+8)*68 + kb+tg  ];
            alo[2] = Plo[(r+g  )*68 + kb+tg+4];
            alo[3] = Plo[(r+g+8)*68 + kb+tg+4];
            #pragma unroll
            for (int nf = 0; nf < 4; nf++) {
                int cn = wc*32 + nf*8 + g;
                uint32_t bh0 = Vhi[(kb+tg  )*72 + cn];
                uint32_t bh1 = Vhi[(kb+tg+4)*72 + cn];
                uint32_t bl0 = Vlo[(kb+tg  )*72 + cn];
                uint32_t bl1 = Vlo[(kb+tg+4)*72 + cn];
                mma_tf32(acc[nf], ahi, bh0, bh1);
                mma_tf32(acc[nf], ahi, bl0, bl1);
                mma_tf32(acc[nf], alo, bh0, bh1);
            }
        }
    }

    // epilogue: element (query i = wr*16+g(+8), d = wc*32+nf*8+tg*2(+1))
    #pragma unroll
    for (int nf = 0; nf < 4; nf++) {
        int d0c = wc*32 + nf*8 + tg*2;
        int r0 = i0 + wr*16 + g;
        *(float2*)&ctx[base + (size_t)r0*Hh + d0c]     = make_float2(acc[nf][0], acc[nf][1]);
        *(float2*)&ctx[base + (size_t)(r0+8)*Hh + d0c] = make_float2(acc[nf][2], acc[nf][3]);
    }
}

// ---------------- head: avg, pooled, classifier ----------------
__global__ void avg_kernel(const float* __restrict__ x, float* __restrict__ avg) {
    int b = blockIdx.x, hcol = threadIdx.x;
    float s = 0.0f;
    for (int ss = 0; ss < Ss; ss++) s += x[((size_t)(b*Ss + ss))*Hh + hcol];
    avg[b*Hh + hcol] = s * (1.0f/512.0f);
}

__global__ __launch_bounds__(128) void pool_kernel(
    const float* __restrict__ x, const float* __restrict__ pw,
    const float* __restrict__ pb, float* __restrict__ pool)
{
    int b = blockIdx.y;
    int o = blockIdx.x*128 + threadIdx.x;
    __shared__ float xb[768];
    for (int j = threadIdx.x; j < 768; j += 128) xb[j] = x[(size_t)(b*Ss)*Hh + j];
    __syncthreads();
    float s = 0.0f;
    for (int hcol = 0; hcol < 768; hcol++) s += xb[hcol]*pw[(size_t)hcol*Hh + o];
    pool[b*Hh + o] = tanhf(s + pb[o]);
}

__global__ void out_kernel(const float* __restrict__ avg, const float* __restrict__ pool,
                           const float* __restrict__ cw, const float* __restrict__ cb,
                           float* __restrict__ out)
{
    int b = blockIdx.x;
    int tid = threadIdx.x;
    int c = tid >> 5, lane = tid & 31;
    if (c >= NCc) return;
    float s = 0.0f;
    for (int t = lane; t < 2*Hh; t += 32) {
        float xv = (t < Hh) ? avg[b*Hh + t] : pool[b*Hh + t - Hh];
        s += xv * cw[(size_t)t*NCc + c];
    }
    for (int o = 16; o > 0; o >>= 1) s += __shfl_xor_sync(0xffffffff, s, o);
    if (lane == 0) out[b*NCc + c] = s + cb[c];
}

// ---------------- launch ----------------
extern "C" void kernel_launch(void* const* d_in, const int* in_sizes, int n_in,
                              void* d_out, int out_size)
{
    const int*   ids   = (const int*)  d_in[0];
    const int*   mask  = (const int*)  d_in[1];
    const float* we    = (const float*)d_in[2];
    const float* pe    = (const float*)d_in[3];
    const float* te    = (const float*)d_in[4];
    const float* lng   = (const float*)d_in[5];
    const float* lnb   = (const float*)d_in[6];
    const float* Wq    = (const float*)d_in[7];
    const float* bq    = (const float*)d_in[8];
    const float* Wk    = (const float*)d_in[9];
    const float* bk    = (const float*)d_in[10];
    const float* Wv    = (const float*)d_in[11];
    const float* bv    = (const float*)d_in[12];
    const float* Wo    = (const float*)d_in[13];
    const float* bo    = (const float*)d_in[14];
    const float* ln1g  = (const float*)d_in[15];
    const float* ln1b  = (const float*)d_in[16];
    const float* W1    = (const float*)d_in[17];
    const float* b1    = (const float*)d_in[18];
    const float* W2    = (const float*)d_in[19];
    const float* b2    = (const float*)d_in[20];
    const float* ln2g  = (const float*)d_in[21];
    const float* ln2b  = (const float*)d_in[22];
    const float* pw    = (const float*)d_in[23];
    const float* pb    = (const float*)d_in[24];
    const float* cw    = (const float*)d_in[25];
    const float* cb    = (const float*)d_in[26];
    float* out = (float*)d_out;

    float *x, *q, *k, *v, *ctx, *t, *ff, *tab, *avg, *pool, *S, *wbin;
    cudaGetSymbolAddress((void**)&x,    g_x);
    cudaGetSymbolAddress((void**)&q,    g_q);
    cudaGetSymbolAddress((void**)&k,    g_k);
    cudaGetSymbolAddress((void**)&v,    g_v);
    cudaGetSymbolAddress((void**)&ctx,  g_ctx);
    cudaGetSymbolAddress((void**)&t,    g_t);
    cudaGetSymbolAddress((void**)&ff,   g_ff);
    cudaGetSymbolAddress((void**)&tab,  g_tab);
    cudaGetSymbolAddress((void**)&avg,  g_avg);
    cudaGetSymbolAddress((void**)&pool, g_pool);
    cudaGetSymbolAddress((void**)&S,    g_S);
    cudaGetSymbolAddress((void**)&wbin, g_wbin);

    cudaFuncSetAttribute(attn_fused_kernel, cudaFuncAttributeMaxDynamicSharedMemorySize, FS_BYTES);
    cudaFuncSetAttribute(attn_ctx_kernel,   cudaFuncAttributeMaxDynamicSharedMemorySize, CS_BYTES);

    tab_init_kernel<<<1, 256>>>(tab);
    embed_ln_kernel<<<MM, 256>>>(ids, we, pe, te, lng, lnb, x);

    dim3 gH(Hh/128, MM/128);     // (6, 32)
    dim3 gF(FFf/128, MM/128);    // (24, 32)
    dim3 gQKV(18, MM/128);
    dim3 gA(Ss/64, NHh, Bb);     // (8, 12, 8)

    for (int l = 0; l < Ll; l++) {
        tgemm_qkv_kernel<<<gQKV, 256>>>(x,
            Wq + (size_t)l*Hh*Hh, Wk + (size_t)l*Hh*Hh, Wv + (size_t)l*Hh*Hh,
            bq + l*Hh, bk + l*Hh, bv + l*Hh, q, k, v);
        attn_fused_kernel<<<gA, 256, FS_BYTES>>>(q, k, tab, mask, S, wbin);
        attn_ctx_kernel<<<gA, 256, CS_BYTES>>>(S, v, wbin, tab, ctx);
        tgemm_kernel<<<gH, 256>>>(ctx, Wo + (size_t)l*Hh*Hh, bo + l*Hh, t, Hh, Hh, 0);
        add_ln_kernel<<<MM, 256>>>(x, t, ln1g + l*Hh, ln1b + l*Hh, x);
        tgemm_kernel<<<gF, 256>>>(x, W1 + (size_t)l*Hh*FFf, b1 + l*FFf, ff, FFf, Hh, 1);
        tgemm_kernel<<<gH, 256>>>(ff, W2 + (size_t)l*FFf*Hh, b2 + l*Hh, t, Hh, FFf, 0);
        add_ln_kernel<<<MM, 256>>>(x, t, ln2g + l*Hh, ln2b + l*Hh, x);
    }

    avg_kernel<<<Bb, Hh>>>(x, avg);
    pool_kernel<<<dim3(6, Bb), 128>>>(x, pw, pb, pool);
    out_kernel<<<Bb, 192>>>(avg, pool, cw, cb, out);
}